// round 12
// baseline (speedup 1.0000x reference)
#include <cuda_runtime.h>
#include <cuda_fp16.h>
#include <math.h>
#include <stdint.h>

#define NROWS 8192
#define DIM   1024
#define BM    128
#define BN    128
#define BK    64                              // fp16 elems per chunk (128 B rows)
#define NSTAGE 3
#define NITER (DIM / BK)                      // 16
#define JT    (NROWS / BN)                    // 64
#define NFBLK (NROWS / 128)                   // 64 finalize blocks
#define STAGE_A_BYTES (BM * BK * 2)           // 16384
#define STAGE_BYTES   (2 * STAGE_A_BYTES)     // 32768
#define SMEM_TOTAL    (NSTAGE * STAGE_BYTES)  // 98304
#define NCONV 1024                            // conversion chunks (16 rows each)
#define NTILE (JT * (NROWS / BM))             // 4096 gemm tiles
#define NTICK (NCONV + NTILE)
#define NPERS 304                             // persistent CTAs (152 SM x 2)

// ---------------- device scratch (static zero-init; reset by finalize) -----
__device__ __align__(1024) __half g_zh[2 * NROWS * DIM];
__device__ float g_diag[NROWS];
__device__ float g_pe[(size_t)JT * NROWS];
__device__ float g_bl[NFBLK];
__device__ float g_bp[NFBLK];
__device__ unsigned int g_cnt;
__device__ unsigned int g_tick;
__device__ unsigned int g_blkdone[128];       // [0..63]=x1 blocks, [64..127]=x2

// ---------------- PTX helpers ----------------
__device__ __forceinline__ uint32_t smem_u32(const void* p) {
    uint32_t a;
    asm("{ .reg .u64 t; cvta.to.shared.u64 t, %1; cvt.u32.u64 %0, t; }" : "=r"(a) : "l"(p));
    return a;
}
#define CPA16(dst, src) \
    asm volatile("cp.async.cg.shared.global [%0], [%1], 16;" :: "r"(dst), "l"(src) : "memory")
#define CPA_COMMIT() asm volatile("cp.async.commit_group;" ::: "memory")
#define CPA_WAIT1()  asm volatile("cp.async.wait_group 1;" ::: "memory")
#define CPA_WAIT0()  asm volatile("cp.async.wait_group 0;" ::: "memory")

__device__ __forceinline__ void ldsm4(uint32_t* r, uint32_t addr) {
    asm volatile("ldmatrix.sync.aligned.m8n8.x4.shared.b16 {%0,%1,%2,%3}, [%4];"
        : "=r"(r[0]), "=r"(r[1]), "=r"(r[2]), "=r"(r[3]) : "r"(addr));
}
__device__ __forceinline__ void mma16816(float* d, const uint32_t* a, const uint32_t* b) {
    asm volatile(
        "mma.sync.aligned.m16n8k16.row.col.f32.f16.f16.f32 "
        "{%0,%1,%2,%3}, {%4,%5,%6,%7}, {%8,%9}, {%0,%1,%2,%3};"
        : "+f"(d[0]), "+f"(d[1]), "+f"(d[2]), "+f"(d[3])
        : "r"(a[0]), "r"(a[1]), "r"(a[2]), "r"(a[3]), "r"(b[0]), "r"(b[1]));
}

// ---------------------------------------------------------------------------
// Conversion chunk: 16 rows -> pre-normalized fp16; one warp per 2 rows.
// ---------------------------------------------------------------------------
__device__ __forceinline__ void conv_chunk(const float* __restrict__ z, int base_row,
                                           int warp, int lane) {
    int row0 = base_row + warp * 2;
    const float* p0 = z + (size_t)row0 * DIM;
    const float* p1 = p0 + DIM;
    float4 v0[8], v1[8];
    float s0 = 0.f, s1 = 0.f;
    #pragma unroll
    for (int i = 0; i < 8; i++) {
        float4 t0 = *reinterpret_cast<const float4*>(p0 + (i >> 1) * 256 + lane * 8 + (i & 1) * 4);
        float4 t1 = *reinterpret_cast<const float4*>(p1 + (i >> 1) * 256 + lane * 8 + (i & 1) * 4);
        v0[i] = t0; v1[i] = t1;
        s0 += t0.x * t0.x + t0.y * t0.y + t0.z * t0.z + t0.w * t0.w;
        s1 += t1.x * t1.x + t1.y * t1.y + t1.z * t1.z + t1.w * t1.w;
    }
    #pragma unroll
    for (int o = 16; o; o >>= 1) {
        s0 += __shfl_xor_sync(0xffffffffu, s0, o);
        s1 += __shfl_xor_sync(0xffffffffu, s1, o);
    }
    float inv0 = rsqrtf(s0), inv1 = rsqrtf(s1);
    __half* ob0 = g_zh + (size_t)row0 * DIM;
    __half* ob1 = ob0 + DIM;
    #pragma unroll
    for (int seg = 0; seg < 4; seg++) {
        uint4 pk;
        __half2 a0 = __floats2half2_rn(v0[seg*2].x * inv0,   v0[seg*2].y * inv0);
        __half2 a1 = __floats2half2_rn(v0[seg*2].z * inv0,   v0[seg*2].w * inv0);
        __half2 a2 = __floats2half2_rn(v0[seg*2+1].x * inv0, v0[seg*2+1].y * inv0);
        __half2 a3 = __floats2half2_rn(v0[seg*2+1].z * inv0, v0[seg*2+1].w * inv0);
        pk.x = *reinterpret_cast<uint32_t*>(&a0);
        pk.y = *reinterpret_cast<uint32_t*>(&a1);
        pk.z = *reinterpret_cast<uint32_t*>(&a2);
        pk.w = *reinterpret_cast<uint32_t*>(&a3);
        *reinterpret_cast<uint4*>(ob0 + seg * 256 + lane * 8) = pk;
        __half2 b0 = __floats2half2_rn(v1[seg*2].x * inv1,   v1[seg*2].y * inv1);
        __half2 b1 = __floats2half2_rn(v1[seg*2].z * inv1,   v1[seg*2].w * inv1);
        __half2 b2 = __floats2half2_rn(v1[seg*2+1].x * inv1, v1[seg*2+1].y * inv1);
        __half2 b3 = __floats2half2_rn(v1[seg*2+1].z * inv1, v1[seg*2+1].w * inv1);
        pk.x = *reinterpret_cast<uint32_t*>(&b0);
        pk.y = *reinterpret_cast<uint32_t*>(&b1);
        pk.z = *reinterpret_cast<uint32_t*>(&b2);
        pk.w = *reinterpret_cast<uint32_t*>(&b3);
        *reinterpret_cast<uint4*>(ob1 + seg * 256 + lane * 8) = pk;
    }
}

// ---------------------------------------------------------------------------
// Persistent fused kernel: tickets 0..NCONV-1 convert (x2 first, then x1);
// tickets NCONV..NTICK-1 are GEMM tiles gated on per-block done flags.
// ---------------------------------------------------------------------------
__global__ __launch_bounds__(256, 2) void persist_kernel(const float* __restrict__ z) {
    extern __shared__ char smem[];
    __shared__ unsigned int stile;
    const uint32_t sb = smem_u32(smem);
    const int tid = threadIdx.x;
    const int warp = tid >> 5, lane = tid & 31;
    const int wy = warp >> 2, wx = warp & 3;        // 2 x 4 warp grid (GEMM)

    // lane-invariant pieces (GEMM)
    const int row0 = tid >> 3, ch0 = tid & 7;
    uint32_t s_off[4];
    #pragma unroll
    for (int r = 0; r < 4; r++) {
        int row = row0 + r * 32;
        s_off[r] = row * 128 + (ch0 ^ (row & 7)) * 16;
    }
    const int rl  = lane & 15;
    const int ahi = lane >> 4;
    const int nl  = (lane & 7) | ((lane >> 4) << 3);
    const int bhi = (lane >> 3) & 1;

    for (;;) {
        if (tid == 0) stile = atomicAdd(&g_tick, 1u);
        __syncthreads();
        const unsigned int t = stile;
        if (t >= NTICK) break;

        if (t < NCONV) {
            // -------- conversion ticket --------
            int base_row, blk;
            if (t < 512) { base_row = NROWS + (int)t * 16; blk = 64 + ((int)t >> 3); }
            else         { base_row = ((int)t - 512) * 16; blk = ((int)t - 512) >> 3; }
            conv_chunk(z, base_row, warp, lane);
            __syncthreads();                       // all stores done
            if (tid == 0) {
                __threadfence();                   // release
                atomicAdd(&g_blkdone[blk], 1u);
            }
            __syncthreads();
            continue;
        }

        // -------- GEMM tile --------
        const int tile = (int)(t - NCONV);
        const int bi = tile >> 6, bj = tile & 63;
        if (tid == 0) {
            while (atomicAdd(&g_blkdone[bi], 0u) < 8u) {}
            while (atomicAdd(&g_blkdone[64 + bj], 0u) < 8u) {}
            __threadfence();                       // acquire
        }
        __syncthreads();

        const char* Ag = (const char*)(g_zh + (size_t)bi * BM * DIM);
        const char* Bg = (const char*)(g_zh + (size_t)(NROWS + bj * BN) * DIM);
        size_t g_off[4];
        #pragma unroll
        for (int r = 0; r < 4; r++)
            g_off[r] = (size_t)(row0 + r * 32) * DIM * 2 + ch0 * 16;

        float acc[4][4][4];
        #pragma unroll
        for (int mt = 0; mt < 4; mt++)
            #pragma unroll
            for (int nt = 0; nt < 4; nt++)
                #pragma unroll
                for (int q = 0; q < 4; q++) acc[mt][nt][q] = 0.f;

        #pragma unroll
        for (int s = 0; s < NSTAGE - 1; s++) {
            uint32_t As = sb + s * STAGE_BYTES;
            uint32_t Bs = As + STAGE_A_BYTES;
            size_t kb = (size_t)(s * BK) * 2;
            #pragma unroll
            for (int r = 0; r < 4; r++) {
                CPA16(As + s_off[r], Ag + g_off[r] + kb);
                CPA16(Bs + s_off[r], Bg + g_off[r] + kb);
            }
            CPA_COMMIT();
        }

        for (int kc = 0; kc < NITER; kc++) {
            const int st = kc % NSTAGE;
            if (kc < NITER - 1) { CPA_WAIT1(); } else { CPA_WAIT0(); }
            __syncthreads();
            if (kc + NSTAGE - 1 < NITER) {
                const int sn = (kc + NSTAGE - 1) % NSTAGE;
                uint32_t As = sb + sn * STAGE_BYTES;
                uint32_t Bs = As + STAGE_A_BYTES;
                size_t kb = (size_t)((kc + NSTAGE - 1) * BK) * 2;
                #pragma unroll
                for (int r = 0; r < 4; r++) {
                    CPA16(As + s_off[r], Ag + g_off[r] + kb);
                    CPA16(Bs + s_off[r], Bg + g_off[r] + kb);
                }
                CPA_COMMIT();
            }
            const uint32_t As = sb + st * STAGE_BYTES;
            const uint32_t Bs = As + STAGE_A_BYTES;
            #pragma unroll
            for (int ks = 0; ks < 4; ks++) {
                uint32_t a[4][4], b[2][4];
                uint32_t a_addr = As + (wy * 64 + rl) * 128 + (((ks * 2 + ahi) ^ (rl & 7)) * 16);
                #pragma unroll
                for (int mt = 0; mt < 4; mt++) ldsm4(a[mt], a_addr + mt * 2048);
                uint32_t b_addr = Bs + (wx * 32 + nl) * 128 + (((ks * 2 + bhi) ^ (nl & 7)) * 16);
                #pragma unroll
                for (int p = 0; p < 2; p++) ldsm4(b[p], b_addr + p * 2048);
                #pragma unroll
                for (int mt = 0; mt < 4; mt++)
                    #pragma unroll
                    for (int nt = 0; nt < 4; nt++)
                        mma16816(acc[mt][nt], a[mt], &b[nt >> 1][(nt & 1) * 2]);
            }
        }

        // epilogue: exp row-sums + diagonal
        __syncthreads();
        float* sred = (float*)smem;
        const bool isdiag = (bi == bj);
        #pragma unroll
        for (int mt = 0; mt < 4; mt++) {
            int ra = wy * 64 + mt * 16 + (lane >> 2);
            float sA = 0.f, sB = 0.f;
            #pragma unroll
            for (int nt = 0; nt < 4; nt++) {
                int c0 = wx * 32 + nt * 8 + 2 * (lane & 3);
                float v0 = acc[mt][nt][0], v1 = acc[mt][nt][1];
                float v2 = acc[mt][nt][2], v3 = acc[mt][nt][3];
                sA += __expf(v0) + __expf(v1);
                sB += __expf(v2) + __expf(v3);
                if (isdiag) {
                    if (ra == c0)         g_diag[bi * BM + ra] = v0;
                    if (ra == c0 + 1)     g_diag[bi * BM + ra] = v1;
                    if (ra + 8 == c0)     g_diag[bi * BM + ra + 8] = v2;
                    if (ra + 8 == c0 + 1) g_diag[bi * BM + ra + 8] = v3;
                }
            }
            sA += __shfl_xor_sync(0xffffffffu, sA, 1);
            sA += __shfl_xor_sync(0xffffffffu, sA, 2);
            sB += __shfl_xor_sync(0xffffffffu, sB, 1);
            sB += __shfl_xor_sync(0xffffffffu, sB, 2);
            if ((lane & 3) == 0) {
                sred[ra * 4 + wx] = sA;
                sred[(ra + 8) * 4 + wx] = sB;
            }
        }
        __syncthreads();
        if (tid < BM) {
            float s = sred[tid * 4 + 0] + sred[tid * 4 + 1]
                    + sred[tid * 4 + 2] + sred[tid * 4 + 3];
            g_pe[(size_t)bj * NROWS + bi * BM + tid] = s;
        }
        __syncthreads();                           // protect sred before next tile
    }
}

// ---------------------------------------------------------------------------
// Finalize (ALPHA=1 -> alpha=p_ij, BETA=0). Last block reduces + resets state.
// ---------------------------------------------------------------------------
__global__ __launch_bounds__(1024) void finalize_kernel(float* __restrict__ out) {
    __shared__ float spart[8][128];
    __shared__ float sl[128], sp[128];
    __shared__ bool is_last;
    int rl = threadIdx.x & 127, tg = threadIdx.x >> 7;
    int r = blockIdx.x * 128 + rl;
    float se = 0.f;
    #pragma unroll
    for (int t = tg * 8; t < tg * 8 + 8; t++) se += g_pe[(size_t)t * NROWS + r];
    spart[tg][rl] = se;
    __syncthreads();
    if (threadIdx.x < 128) {
        float tot = 0.f;
        #pragma unroll
        for (int t = 0; t < 8; t++) tot += spart[t][rl];
        float pos = g_diag[r];
        float pe  = __expf(pos);               // bitwise-identical to epilogue term
        float p   = pe / (tot - pe);
        sl[rl] = -logf(p) - p * pos;
        sp[rl] = p;
    }
    __syncthreads();
    #pragma unroll
    for (int o = 64; o; o >>= 1) {
        if (threadIdx.x < o) {
            sl[threadIdx.x] += sl[threadIdx.x + o];
            sp[threadIdx.x] += sp[threadIdx.x + o];
        }
        __syncthreads();
    }
    if (threadIdx.x == 0) {
        g_bl[blockIdx.x] = sl[0];
        g_bp[blockIdx.x] = sp[0];
        __threadfence();
        unsigned int prev = atomicAdd(&g_cnt, 1u);
        is_last = (prev == NFBLK - 1);
    }
    __syncthreads();
    if (is_last && threadIdx.x == 0) {
        float tl = 0.f, tp = 0.f;
        #pragma unroll
        for (int b = 0; b < NFBLK; b++) { tl += g_bl[b]; tp += g_bp[b]; }
        out[0] = tl / (float)NROWS;
        out[1] = tp / (float)NROWS;
        // reset persistent state for next graph replay
        g_tick = 0;
        g_cnt  = 0;
        #pragma unroll
        for (int b = 0; b < 128; b++) g_blkdone[b] = 0;
    }
}

// ---------------------------------------------------------------------------
extern "C" void kernel_launch(void* const* d_in, const int* in_sizes, int n_in,
                              void* d_out, int out_size) {
    const float* z = (const float*)d_in[0];
    float* out = (float*)d_out;

    cudaFuncSetAttribute(persist_kernel, cudaFuncAttributeMaxDynamicSharedMemorySize, SMEM_TOTAL);

    persist_kernel<<<NPERS, 256, SMEM_TOTAL>>>(z);
    finalize_kernel<<<NFBLK, 1024>>>(out);
}

// round 13
// speedup vs baseline: 1.9673x; 1.9673x over previous
#include <cuda_runtime.h>
#include <cuda_fp16.h>
#include <math.h>
#include <stdint.h>

#define NROWS 8192
#define DIM   1024
#define BM    128
#define BN    128
#define BK    64                              // fp16 elems per chunk (128 B rows)
#define NSTAGE 3
#define NITER (DIM / BK)                      // 16
#define JT    (NROWS / BN)                    // 64
#define NFBLK (NROWS / 128)                   // 64 finalize blocks
#define STAGE_A_BYTES (BM * BK * 2)           // 16384
#define STAGE_BYTES   (2 * STAGE_A_BYTES)     // 32768
#define SMEM_TOTAL    (NSTAGE * STAGE_BYTES)  // 98304

// ---------------- device scratch ----------------
__device__ __align__(1024) __half g_zh[2 * NROWS * DIM];
__device__ float g_diag[NROWS];
__device__ float g_pe[(size_t)JT * NROWS];
__device__ float g_bl[NFBLK];
__device__ float g_bp[NFBLK];
__device__ unsigned int g_cnt;

// ---------------- PTX helpers ----------------
__device__ __forceinline__ uint32_t smem_u32(const void* p) {
    uint32_t a;
    asm("{ .reg .u64 t; cvta.to.shared.u64 t, %1; cvt.u32.u64 %0, t; }" : "=r"(a) : "l"(p));
    return a;
}
#define CPA16(dst, src) \
    asm volatile("cp.async.cg.shared.global [%0], [%1], 16;" :: "r"(dst), "l"(src) : "memory")
#define CPA_COMMIT() asm volatile("cp.async.commit_group;" ::: "memory")
#define CPA_WAIT1()  asm volatile("cp.async.wait_group 1;" ::: "memory")
#define CPA_WAIT0()  asm volatile("cp.async.wait_group 0;" ::: "memory")

__device__ __forceinline__ void ldsm4(uint32_t* r, uint32_t addr) {
    asm volatile("ldmatrix.sync.aligned.m8n8.x4.shared.b16 {%0,%1,%2,%3}, [%4];"
        : "=r"(r[0]), "=r"(r[1]), "=r"(r[2]), "=r"(r[3]) : "r"(addr));
}
__device__ __forceinline__ void mma16816(float* d, const uint32_t* a, const uint32_t* b) {
    asm volatile(
        "mma.sync.aligned.m16n8k16.row.col.f32.f16.f16.f32 "
        "{%0,%1,%2,%3}, {%4,%5,%6,%7}, {%8,%9}, {%0,%1,%2,%3};"
        : "+f"(d[0]), "+f"(d[1]), "+f"(d[2]), "+f"(d[3])
        : "r"(a[0]), "r"(a[1]), "r"(a[2]), "r"(a[3]), "r"(b[0]), "r"(b[1]));
}

// ---------------------------------------------------------------------------
// 1) Fused norms + convert to pre-normalized fp16 (STG.128 stores).
// ---------------------------------------------------------------------------
__global__ __launch_bounds__(256) void normconv_kernel(const float* __restrict__ z) {
    if (blockIdx.x == 0 && threadIdx.x == 0) g_cnt = 0;
    int warp = threadIdx.x >> 5, lane = threadIdx.x & 31;
    int row  = blockIdx.x * 8 + warp;
    const float* p = z + (size_t)row * DIM;
    float4 v[8];
    float s = 0.f;
    #pragma unroll
    for (int seg = 0; seg < 4; seg++) {
        #pragma unroll
        for (int h = 0; h < 2; h++) {
            float4 t = *reinterpret_cast<const float4*>(p + seg * 256 + lane * 8 + h * 4);
            v[seg * 2 + h] = t;
            s += t.x * t.x + t.y * t.y + t.z * t.z + t.w * t.w;
        }
    }
    #pragma unroll
    for (int o = 16; o; o >>= 1) s += __shfl_xor_sync(0xffffffffu, s, o);
    float inv = rsqrtf(s);
    __half* ob = g_zh + (size_t)row * DIM;
    #pragma unroll
    for (int seg = 0; seg < 4; seg++) {
        uint4 pk;
        __half2 h0 = __floats2half2_rn(v[seg*2].x * inv,   v[seg*2].y * inv);
        __half2 h1 = __floats2half2_rn(v[seg*2].z * inv,   v[seg*2].w * inv);
        __half2 h2 = __floats2half2_rn(v[seg*2+1].x * inv, v[seg*2+1].y * inv);
        __half2 h3 = __floats2half2_rn(v[seg*2+1].z * inv, v[seg*2+1].w * inv);
        pk.x = *reinterpret_cast<uint32_t*>(&h0);
        pk.y = *reinterpret_cast<uint32_t*>(&h1);
        pk.z = *reinterpret_cast<uint32_t*>(&h2);
        pk.w = *reinterpret_cast<uint32_t*>(&h3);
        *reinterpret_cast<uint4*>(ob + seg * 256 + lane * 8) = pk;
    }
}

// ---------------------------------------------------------------------------
// 2) HMMA GEMM 128x128x64/iter, 3-stage cp.async, single sync per iter,
//    fused exp epilogue. 8 warps in 2x4 grid, warp tile 64x32. (champion)
// ---------------------------------------------------------------------------
__global__ __launch_bounds__(256, 2) void gemm_kernel() {
    extern __shared__ char smem[];
    const uint32_t sb = smem_u32(smem);
    const int tid = threadIdx.x;
    const int warp = tid >> 5, lane = tid & 31;
    const int wy = warp >> 2, wx = warp & 3;        // 2 x 4 warp grid
    const int bi = blockIdx.y, bj = blockIdx.x;

    const char* Ag = (const char*)(g_zh + (size_t)bi * BM * DIM);
    const char* Bg = (const char*)(g_zh + (size_t)(NROWS + bj * BN) * DIM);

    // cp.async mapping: 128B rows = 8 x 16B chunks; phys = ch ^ (row & 7).
    const int row0 = tid >> 3, ch0 = tid & 7;       // rows 0..31
    uint32_t s_off[4];
    size_t   g_off[4];
    #pragma unroll
    for (int r = 0; r < 4; r++) {
        int row = row0 + r * 32;
        int ph  = ch0 ^ (row & 7);
        s_off[r] = row * 128 + ph * 16;
        g_off[r] = (size_t)row * DIM * 2 + ch0 * 16;
    }

    float acc[4][4][4];
    #pragma unroll
    for (int mt = 0; mt < 4; mt++)
        #pragma unroll
        for (int nt = 0; nt < 4; nt++)
            #pragma unroll
            for (int q = 0; q < 4; q++) acc[mt][nt][q] = 0.f;

    // prologue: stages 0,1
    #pragma unroll
    for (int s = 0; s < NSTAGE - 1; s++) {
        uint32_t As = sb + s * STAGE_BYTES;
        uint32_t Bs = As + STAGE_A_BYTES;
        size_t kb = (size_t)(s * BK) * 2;
        #pragma unroll
        for (int r = 0; r < 4; r++) {
            CPA16(As + s_off[r], Ag + g_off[r] + kb);
            CPA16(Bs + s_off[r], Bg + g_off[r] + kb);
        }
        CPA_COMMIT();
    }

    // ldmatrix lane components
    const int rl  = lane & 15;                  // A row within 16
    const int ahi = lane >> 4;                  // A 16B k-chunk select
    const int nl  = (lane & 7) | ((lane >> 4) << 3);   // B n within 16
    const int bhi = (lane >> 3) & 1;

    for (int kc = 0; kc < NITER; kc++) {
        const int st = kc % NSTAGE;
        if (kc < NITER - 1) { CPA_WAIT1(); } else { CPA_WAIT0(); }
        __syncthreads();
        if (kc + NSTAGE - 1 < NITER) {
            const int sn = (kc + NSTAGE - 1) % NSTAGE;
            uint32_t As = sb + sn * STAGE_BYTES;
            uint32_t Bs = As + STAGE_A_BYTES;
            size_t kb = (size_t)((kc + NSTAGE - 1) * BK) * 2;
            #pragma unroll
            for (int r = 0; r < 4; r++) {
                CPA16(As + s_off[r], Ag + g_off[r] + kb);
                CPA16(Bs + s_off[r], Bg + g_off[r] + kb);
            }
            CPA_COMMIT();
        }
        const uint32_t As = sb + st * STAGE_BYTES;
        const uint32_t Bs = As + STAGE_A_BYTES;
        #pragma unroll
        for (int ks = 0; ks < 4; ks++) {
            uint32_t a[4][4], b[2][4];
            uint32_t a_addr = As + (wy * 64 + rl) * 128 + (((ks * 2 + ahi) ^ (rl & 7)) * 16);
            #pragma unroll
            for (int mt = 0; mt < 4; mt++) ldsm4(a[mt], a_addr + mt * 2048);
            uint32_t b_addr = Bs + (wx * 32 + nl) * 128 + (((ks * 2 + bhi) ^ (nl & 7)) * 16);
            #pragma unroll
            for (int p = 0; p < 2; p++) ldsm4(b[p], b_addr + p * 2048);
            #pragma unroll
            for (int mt = 0; mt < 4; mt++)
                #pragma unroll
                for (int nt = 0; nt < 4; nt++)
                    mma16816(acc[mt][nt], a[mt], &b[nt >> 1][(nt & 1) * 2]);
        }
    }

    // ---------------- epilogue: exp row-sums + diagonal ----------------
    __syncthreads();
    float* sred = (float*)smem;                // 128 rows x 4 wx
    const bool isdiag = (bi == bj);
    #pragma unroll
    for (int mt = 0; mt < 4; mt++) {
        int ra = wy * 64 + mt * 16 + (lane >> 2);
        float sA = 0.f, sB = 0.f;
        #pragma unroll
        for (int nt = 0; nt < 4; nt++) {
            int c0 = wx * 32 + nt * 8 + 2 * (lane & 3);
            float v0 = acc[mt][nt][0], v1 = acc[mt][nt][1];
            float v2 = acc[mt][nt][2], v3 = acc[mt][nt][3];
            sA += __expf(v0) + __expf(v1);
            sB += __expf(v2) + __expf(v3);
            if (isdiag) {
                if (ra == c0)         g_diag[bi * BM + ra] = v0;
                if (ra == c0 + 1)     g_diag[bi * BM + ra] = v1;
                if (ra + 8 == c0)     g_diag[bi * BM + ra + 8] = v2;
                if (ra + 8 == c0 + 1) g_diag[bi * BM + ra + 8] = v3;
            }
        }
        sA += __shfl_xor_sync(0xffffffffu, sA, 1);
        sA += __shfl_xor_sync(0xffffffffu, sA, 2);
        sB += __shfl_xor_sync(0xffffffffu, sB, 1);
        sB += __shfl_xor_sync(0xffffffffu, sB, 2);
        if ((lane & 3) == 0) {
            sred[ra * 4 + wx] = sA;
            sred[(ra + 8) * 4 + wx] = sB;
        }
    }
    __syncthreads();
    if (tid < BM) {
        float s = sred[tid * 4 + 0] + sred[tid * 4 + 1]
                + sred[tid * 4 + 2] + sred[tid * 4 + 3];
        g_pe[(size_t)bj * NROWS + bi * BM + tid] = s;
    }
}

// ---------------------------------------------------------------------------
// 3) Finalize (ALPHA=1 -> alpha=p_ij, BETA=0 -> neg_sim drops).
//    Last-block-done final reduction, fixed order -> deterministic.
// ---------------------------------------------------------------------------
__global__ __launch_bounds__(1024) void finalize_kernel(float* __restrict__ out) {
    __shared__ float spart[8][128];
    __shared__ float sl[128], sp[128];
    __shared__ bool is_last;
    int rl = threadIdx.x & 127, tg = threadIdx.x >> 7;
    int r = blockIdx.x * 128 + rl;
    float se = 0.f;
    #pragma unroll
    for (int t = tg * 8; t < tg * 8 + 8; t++) se += g_pe[(size_t)t * NROWS + r];
    spart[tg][rl] = se;
    __syncthreads();
    if (threadIdx.x < 128) {
        float tot = 0.f;
        #pragma unroll
        for (int t = 0; t < 8; t++) tot += spart[t][rl];
        float pos = g_diag[r];
        float pe  = __expf(pos);               // bitwise-identical to epilogue term
        float p   = pe / (tot - pe);
        sl[rl] = -logf(p) - p * pos;
        sp[rl] = p;
    }
    __syncthreads();
    #pragma unroll
    for (int o = 64; o; o >>= 1) {
        if (threadIdx.x < o) {
            sl[threadIdx.x] += sl[threadIdx.x + o];
            sp[threadIdx.x] += sp[threadIdx.x + o];
        }
        __syncthreads();
    }
    if (threadIdx.x == 0) {
        g_bl[blockIdx.x] = sl[0];
        g_bp[blockIdx.x] = sp[0];
        __threadfence();
        unsigned int prev = atomicAdd(&g_cnt, 1u);
        is_last = (prev == NFBLK - 1);
    }
    __syncthreads();
    if (is_last && threadIdx.x == 0) {
        float tl = 0.f, tp = 0.f;
        #pragma unroll
        for (int b = 0; b < NFBLK; b++) { tl += g_bl[b]; tp += g_bp[b]; }
        out[0] = tl / (float)NROWS;
        out[1] = tp / (float)NROWS;
    }
}

// ---------------------------------------------------------------------------
extern "C" void kernel_launch(void* const* d_in, const int* in_sizes, int n_in,
                              void* d_out, int out_size) {
    const float* z = (const float*)d_in[0];
    float* out = (float*)d_out;

    cudaFuncSetAttribute(gemm_kernel, cudaFuncAttributeMaxDynamicSharedMemorySize, SMEM_TOTAL);

    normconv_kernel<<<2 * NROWS / 8, 256>>>(z);
    gemm_kernel<<<dim3(NROWS / BN, NROWS / BM), 256, SMEM_TOTAL>>>();
    finalize_kernel<<<NFBLK, 1024>>>(out);
}

// round 14
// speedup vs baseline: 2.0030x; 1.0182x over previous
#include <cuda_runtime.h>
#include <cuda_fp16.h>
#include <math.h>
#include <stdint.h>

#define NROWS 8192
#define DIM   1024
#define BM    128
#define BN    128
#define BK    64                              // fp16 elems per chunk (128 B rows)
#define NSTAGE 3
#define NITER (DIM / BK)                      // 16
#define JT    (NROWS / BN)                    // 64
#define NFBLK (NROWS / 128)                   // 64 finalize blocks
#define STAGE_A_BYTES (BM * BK * 2)           // 16384
#define STAGE_BYTES   (2 * STAGE_A_BYTES)     // 32768
#define SMEM_TOTAL    (NSTAGE * STAGE_BYTES)  // 98304
#define LOG2E 1.4426950408889634f
#define LN2   0.6931471805599453f

// ---------------- device scratch ----------------
__device__ __align__(1024) __half g_zh[2 * NROWS * DIM];
__device__ float g_diag[NROWS];               // stores log2e-scaled cosine
__device__ float g_pe[(size_t)JT * NROWS];
__device__ float g_bl[NFBLK];
__device__ float g_bp[NFBLK];
__device__ unsigned int g_cnt;

// ---------------- PTX helpers ----------------
__device__ __forceinline__ uint32_t smem_u32(const void* p) {
    uint32_t a;
    asm("{ .reg .u64 t; cvta.to.shared.u64 t, %1; cvt.u32.u64 %0, t; }" : "=r"(a) : "l"(p));
    return a;
}
#define CPA16(dst, src) \
    asm volatile("cp.async.cg.shared.global [%0], [%1], 16;" :: "r"(dst), "l"(src) : "memory")
#define CPA_COMMIT() asm volatile("cp.async.commit_group;" ::: "memory")
#define CPA_WAIT1()  asm volatile("cp.async.wait_group 1;" ::: "memory")
#define CPA_WAIT0()  asm volatile("cp.async.wait_group 0;" ::: "memory")

__device__ __forceinline__ void ldsm4(uint32_t* r, uint32_t addr) {
    asm volatile("ldmatrix.sync.aligned.m8n8.x4.shared.b16 {%0,%1,%2,%3}, [%4];"
        : "=r"(r[0]), "=r"(r[1]), "=r"(r[2]), "=r"(r[3]) : "r"(addr));
}
__device__ __forceinline__ void mma16816(float* d, const uint32_t* a, const uint32_t* b) {
    asm volatile(
        "mma.sync.aligned.m16n8k16.row.col.f32.f16.f16.f32 "
        "{%0,%1,%2,%3}, {%4,%5,%6,%7}, {%8,%9}, {%0,%1,%2,%3};"
        : "+f"(d[0]), "+f"(d[1]), "+f"(d[2]), "+f"(d[3])
        : "r"(a[0]), "r"(a[1]), "r"(a[2]), "r"(a[3]), "r"(b[0]), "r"(b[1]));
}
// bare ex2 — used in BOTH epilogue and finalize so the diagonal term cancels bitwise
__device__ __forceinline__ float ex2(float x) {
    float r;
    asm("ex2.approx.ftz.f32 %0, %1;" : "=f"(r) : "f"(x));
    return r;
}

// ---------------------------------------------------------------------------
// 1) Fused norms + convert to pre-normalized fp16.
//    x1 rows (row < NROWS) are additionally scaled by log2(e) so the MMA
//    output is log2e*cos and the epilogue exp needs no argument multiply.
// ---------------------------------------------------------------------------
__global__ __launch_bounds__(256) void normconv_kernel(const float* __restrict__ z) {
    if (blockIdx.x == 0 && threadIdx.x == 0) g_cnt = 0;
    int warp = threadIdx.x >> 5, lane = threadIdx.x & 31;
    int row  = blockIdx.x * 8 + warp;
    const float* p = z + (size_t)row * DIM;
    float4 v[8];
    float s = 0.f;
    #pragma unroll
    for (int seg = 0; seg < 4; seg++) {
        #pragma unroll
        for (int h = 0; h < 2; h++) {
            float4 t = *reinterpret_cast<const float4*>(p + seg * 256 + lane * 8 + h * 4);
            v[seg * 2 + h] = t;
            s += t.x * t.x + t.y * t.y + t.z * t.z + t.w * t.w;
        }
    }
    #pragma unroll
    for (int o = 16; o; o >>= 1) s += __shfl_xor_sync(0xffffffffu, s, o);
    float inv = rsqrtf(s);
    if (row < NROWS) inv *= LOG2E;             // fold exp's log2e into x1
    __half* ob = g_zh + (size_t)row * DIM;
    #pragma unroll
    for (int seg = 0; seg < 4; seg++) {
        uint4 pk;
        __half2 h0 = __floats2half2_rn(v[seg*2].x * inv,   v[seg*2].y * inv);
        __half2 h1 = __floats2half2_rn(v[seg*2].z * inv,   v[seg*2].w * inv);
        __half2 h2 = __floats2half2_rn(v[seg*2+1].x * inv, v[seg*2+1].y * inv);
        __half2 h3 = __floats2half2_rn(v[seg*2+1].z * inv, v[seg*2+1].w * inv);
        pk.x = *reinterpret_cast<uint32_t*>(&h0);
        pk.y = *reinterpret_cast<uint32_t*>(&h1);
        pk.z = *reinterpret_cast<uint32_t*>(&h2);
        pk.w = *reinterpret_cast<uint32_t*>(&h3);
        *reinterpret_cast<uint4*>(ob + seg * 256 + lane * 8) = pk;
    }
}

// ---------------------------------------------------------------------------
// 2) HMMA GEMM 128x128x64/iter, 3-stage cp.async, single sync per iter,
//    fused ex2 epilogue. 8 warps in 2x4 grid, warp tile 64x32. (champion)
// ---------------------------------------------------------------------------
__global__ __launch_bounds__(256, 2) void gemm_kernel() {
    extern __shared__ char smem[];
    const uint32_t sb = smem_u32(smem);
    const int tid = threadIdx.x;
    const int warp = tid >> 5, lane = tid & 31;
    const int wy = warp >> 2, wx = warp & 3;        // 2 x 4 warp grid
    const int bi = blockIdx.y, bj = blockIdx.x;

    const char* Ag = (const char*)(g_zh + (size_t)bi * BM * DIM);
    const char* Bg = (const char*)(g_zh + (size_t)(NROWS + bj * BN) * DIM);

    // cp.async mapping: 128B rows = 8 x 16B chunks; phys = ch ^ (row & 7).
    const int row0 = tid >> 3, ch0 = tid & 7;       // rows 0..31
    uint32_t s_off[4];
    size_t   g_off[4];
    #pragma unroll
    for (int r = 0; r < 4; r++) {
        int row = row0 + r * 32;
        int ph  = ch0 ^ (row & 7);
        s_off[r] = row * 128 + ph * 16;
        g_off[r] = (size_t)row * DIM * 2 + ch0 * 16;
    }

    float acc[4][4][4];
    #pragma unroll
    for (int mt = 0; mt < 4; mt++)
        #pragma unroll
        for (int nt = 0; nt < 4; nt++)
            #pragma unroll
            for (int q = 0; q < 4; q++) acc[mt][nt][q] = 0.f;

    // prologue: stages 0,1
    #pragma unroll
    for (int s = 0; s < NSTAGE - 1; s++) {
        uint32_t As = sb + s * STAGE_BYTES;
        uint32_t Bs = As + STAGE_A_BYTES;
        size_t kb = (size_t)(s * BK) * 2;
        #pragma unroll
        for (int r = 0; r < 4; r++) {
            CPA16(As + s_off[r], Ag + g_off[r] + kb);
            CPA16(Bs + s_off[r], Bg + g_off[r] + kb);
        }
        CPA_COMMIT();
    }

    // ldmatrix lane components
    const int rl  = lane & 15;                  // A row within 16
    const int ahi = lane >> 4;                  // A 16B k-chunk select
    const int nl  = (lane & 7) | ((lane >> 4) << 3);   // B n within 16
    const int bhi = (lane >> 3) & 1;

    for (int kc = 0; kc < NITER; kc++) {
        const int st = kc % NSTAGE;
        if (kc < NITER - 1) { CPA_WAIT1(); } else { CPA_WAIT0(); }
        __syncthreads();
        if (kc + NSTAGE - 1 < NITER) {
            const int sn = (kc + NSTAGE - 1) % NSTAGE;
            uint32_t As = sb + sn * STAGE_BYTES;
            uint32_t Bs = As + STAGE_A_BYTES;
            size_t kb = (size_t)((kc + NSTAGE - 1) * BK) * 2;
            #pragma unroll
            for (int r = 0; r < 4; r++) {
                CPA16(As + s_off[r], Ag + g_off[r] + kb);
                CPA16(Bs + s_off[r], Bg + g_off[r] + kb);
            }
            CPA_COMMIT();
        }
        const uint32_t As = sb + st * STAGE_BYTES;
        const uint32_t Bs = As + STAGE_A_BYTES;
        #pragma unroll
        for (int ks = 0; ks < 4; ks++) {
            uint32_t a[4][4], b[2][4];
            uint32_t a_addr = As + (wy * 64 + rl) * 128 + (((ks * 2 + ahi) ^ (rl & 7)) * 16);
            #pragma unroll
            for (int mt = 0; mt < 4; mt++) ldsm4(a[mt], a_addr + mt * 2048);
            uint32_t b_addr = Bs + (wx * 32 + nl) * 128 + (((ks * 2 + bhi) ^ (nl & 7)) * 16);
            #pragma unroll
            for (int p = 0; p < 2; p++) ldsm4(b[p], b_addr + p * 2048);
            #pragma unroll
            for (int mt = 0; mt < 4; mt++)
                #pragma unroll
                for (int nt = 0; nt < 4; nt++)
                    mma16816(acc[mt][nt], a[mt], &b[nt >> 1][(nt & 1) * 2]);
        }
    }

    // ---------------- epilogue: ex2 row-sums + diagonal (scaled) -----------
    __syncthreads();
    float* sred = (float*)smem;                // 128 rows x 4 wx
    const bool isdiag = (bi == bj);
    #pragma unroll
    for (int mt = 0; mt < 4; mt++) {
        int ra = wy * 64 + mt * 16 + (lane >> 2);
        float sA = 0.f, sB = 0.f;
        #pragma unroll
        for (int nt = 0; nt < 4; nt++) {
            int c0 = wx * 32 + nt * 8 + 2 * (lane & 3);
            float v0 = acc[mt][nt][0], v1 = acc[mt][nt][1];
            float v2 = acc[mt][nt][2], v3 = acc[mt][nt][3];
            sA += ex2(v0) + ex2(v1);
            sB += ex2(v2) + ex2(v3);
            if (isdiag) {
                if (ra == c0)         g_diag[bi * BM + ra] = v0;
                if (ra == c0 + 1)     g_diag[bi * BM + ra] = v1;
                if (ra + 8 == c0)     g_diag[bi * BM + ra + 8] = v2;
                if (ra + 8 == c0 + 1) g_diag[bi * BM + ra + 8] = v3;
            }
        }
        sA += __shfl_xor_sync(0xffffffffu, sA, 1);
        sA += __shfl_xor_sync(0xffffffffu, sA, 2);
        sB += __shfl_xor_sync(0xffffffffu, sB, 1);
        sB += __shfl_xor_sync(0xffffffffu, sB, 2);
        if ((lane & 3) == 0) {
            sred[ra * 4 + wx] = sA;
            sred[(ra + 8) * 4 + wx] = sB;
        }
    }
    __syncthreads();
    if (tid < BM) {
        float s = sred[tid * 4 + 0] + sred[tid * 4 + 1]
                + sred[tid * 4 + 2] + sred[tid * 4 + 3];
        g_pe[(size_t)bj * NROWS + bi * BM + tid] = s;
    }
}

// ---------------------------------------------------------------------------
// 3) Finalize (ALPHA=1 -> alpha=p_ij, BETA=0 -> neg_sim drops).
//    pe = ex2(scaled diag) is bitwise-identical to the epilogue's term, so
//    the row-sum subtraction cancels exactly. pos recovered via * ln2.
// ---------------------------------------------------------------------------
__global__ __launch_bounds__(1024) void finalize_kernel(float* __restrict__ out) {
    __shared__ float spart[8][128];
    __shared__ float sl[128], sp[128];
    __shared__ bool is_last;
    int rl = threadIdx.x & 127, tg = threadIdx.x >> 7;
    int r = blockIdx.x * 128 + rl;
    float se = 0.f;
    #pragma unroll
    for (int t = tg * 8; t < tg * 8 + 8; t++) se += g_pe[(size_t)t * NROWS + r];
    spart[tg][rl] = se;
    __syncthreads();
    if (threadIdx.x < 128) {
        float tot = 0.f;
        #pragma unroll
        for (int t = 0; t < 8; t++) tot += spart[t][rl];
        float dv  = g_diag[r];                 // log2e-scaled cosine
        float pe  = ex2(dv);                   // bitwise-identical to epilogue term
        float pos = dv * LN2;                  // true cosine similarity
        float p   = pe / (tot - pe);
        sl[rl] = -logf(p) - p * pos;
        sp[rl] = p;
    }
    __syncthreads();
    #pragma unroll
    for (int o = 64; o; o >>= 1) {
        if (threadIdx.x < o) {
            sl[threadIdx.x] += sl[threadIdx.x + o];
            sp[threadIdx.x] += sp[threadIdx.x + o];
        }
        __syncthreads();
    }
    if (threadIdx.x == 0) {
        g_bl[blockIdx.x] = sl[0];
        g_bp[blockIdx.x] = sp[0];
        __threadfence();
        unsigned int prev = atomicAdd(&g_cnt, 1u);
        is_last = (prev == NFBLK - 1);
    }
    __syncthreads();
    if (is_last && threadIdx.x == 0) {
        float tl = 0.f, tp = 0.f;
        #pragma unroll
        for (int b = 0; b < NFBLK; b++) { tl += g_bl[b]; tp += g_bp[b]; }
        out[0] = tl / (float)NROWS;
        out[1] = tp / (float)NROWS;
    }
}

// ---------------------------------------------------------------------------
extern "C" void kernel_launch(void* const* d_in, const int* in_sizes, int n_in,
                              void* d_out, int out_size) {
    const float* z = (const float*)d_in[0];
    float* out = (float*)d_out;

    cudaFuncSetAttribute(gemm_kernel, cudaFuncAttributeMaxDynamicSharedMemorySize, SMEM_TOTAL);

    normconv_kernel<<<2 * NROWS / 8, 256>>>(z);
    gemm_kernel<<<dim3(NROWS / BN, NROWS / BM), 256, SMEM_TOTAL>>>();
    finalize_kernel<<<NFBLK, 1024>>>(out);
}

// round 15
// speedup vs baseline: 2.0071x; 1.0021x over previous
#include <cuda_runtime.h>
#include <cuda_fp16.h>
#include <math.h>
#include <stdint.h>

#define NROWS 8192
#define DIM   1024
#define BM    128
#define BN    128
#define BK    64                              // fp16 elems per chunk (128 B rows)
#define NSTAGE 3
#define NITER (DIM / BK)                      // 16
#define JT    (NROWS / BN)                    // 64
#define NFBLK (NROWS / 128)                   // 64 finalize blocks
#define STAGE_A_BYTES (BM * BK * 2)           // 16384
#define STAGE_BYTES   (2 * STAGE_A_BYTES)     // 32768
#define SMEM_TOTAL    (NSTAGE * STAGE_BYTES)  // 98304
#define LOG2E 1.4426950408889634f
#define LN2   0.6931471805599453f

// ---------------- device scratch ----------------
__device__ __align__(1024) __half g_zh[2 * NROWS * DIM];
__device__ float g_diag[NROWS];               // stores log2e-scaled cosine
__device__ float g_pe[(size_t)JT * NROWS];
__device__ float g_bl[NFBLK];
__device__ float g_bp[NFBLK];
__device__ unsigned int g_cnt;

// ---------------- PTX helpers ----------------
__device__ __forceinline__ uint32_t smem_u32(const void* p) {
    uint32_t a;
    asm("{ .reg .u64 t; cvta.to.shared.u64 t, %1; cvt.u32.u64 %0, t; }" : "=r"(a) : "l"(p));
    return a;
}
#define CPA16(dst, src) \
    asm volatile("cp.async.cg.shared.global [%0], [%1], 16;" :: "r"(dst), "l"(src) : "memory")
#define CPA_COMMIT() asm volatile("cp.async.commit_group;" ::: "memory")
#define CPA_WAIT1()  asm volatile("cp.async.wait_group 1;" ::: "memory")
#define CPA_WAIT0()  asm volatile("cp.async.wait_group 0;" ::: "memory")

__device__ __forceinline__ void ldsm4(uint32_t* r, uint32_t addr) {
    asm volatile("ldmatrix.sync.aligned.m8n8.x4.shared.b16 {%0,%1,%2,%3}, [%4];"
        : "=r"(r[0]), "=r"(r[1]), "=r"(r[2]), "=r"(r[3]) : "r"(addr));
}
__device__ __forceinline__ void mma16816(float* d, const uint32_t* a, const uint32_t* b) {
    asm volatile(
        "mma.sync.aligned.m16n8k16.row.col.f32.f16.f16.f32 "
        "{%0,%1,%2,%3}, {%4,%5,%6,%7}, {%8,%9}, {%0,%1,%2,%3};"
        : "+f"(d[0]), "+f"(d[1]), "+f"(d[2]), "+f"(d[3])
        : "r"(a[0]), "r"(a[1]), "r"(a[2]), "r"(a[3]), "r"(b[0]), "r"(b[1]));
}
// bare ex2 — used in BOTH epilogue and finalize so the diagonal term cancels bitwise
__device__ __forceinline__ float ex2(float x) {
    float r;
    asm("ex2.approx.ftz.f32 %0, %1;" : "=f"(r) : "f"(x));
    return r;
}

// ---------------------------------------------------------------------------
// 1) Fused norms + convert to pre-normalized fp16.
//    x1 rows (row < NROWS) are additionally scaled by log2(e) so the MMA
//    output is log2e*cos and the epilogue exp needs no argument multiply.
// ---------------------------------------------------------------------------
__global__ __launch_bounds__(256) void normconv_kernel(const float* __restrict__ z) {
    if (blockIdx.x == 0 && threadIdx.x == 0) g_cnt = 0;
    int warp = threadIdx.x >> 5, lane = threadIdx.x & 31;
    int row  = blockIdx.x * 8 + warp;
    const float* p = z + (size_t)row * DIM;
    float4 v[8];
    float s = 0.f;
    #pragma unroll
    for (int seg = 0; seg < 4; seg++) {
        #pragma unroll
        for (int h = 0; h < 2; h++) {
            float4 t = *reinterpret_cast<const float4*>(p + seg * 256 + lane * 8 + h * 4);
            v[seg * 2 + h] = t;
            s += t.x * t.x + t.y * t.y + t.z * t.z + t.w * t.w;
        }
    }
    #pragma unroll
    for (int o = 16; o; o >>= 1) s += __shfl_xor_sync(0xffffffffu, s, o);
    float inv = rsqrtf(s);
    if (row < NROWS) inv *= LOG2E;             // fold exp's log2e into x1
    __half* ob = g_zh + (size_t)row * DIM;
    #pragma unroll
    for (int seg = 0; seg < 4; seg++) {
        uint4 pk;
        __half2 h0 = __floats2half2_rn(v[seg*2].x * inv,   v[seg*2].y * inv);
        __half2 h1 = __floats2half2_rn(v[seg*2].z * inv,   v[seg*2].w * inv);
        __half2 h2 = __floats2half2_rn(v[seg*2+1].x * inv, v[seg*2+1].y * inv);
        __half2 h3 = __floats2half2_rn(v[seg*2+1].z * inv, v[seg*2+1].w * inv);
        pk.x = *reinterpret_cast<uint32_t*>(&h0);
        pk.y = *reinterpret_cast<uint32_t*>(&h1);
        pk.z = *reinterpret_cast<uint32_t*>(&h2);
        pk.w = *reinterpret_cast<uint32_t*>(&h3);
        *reinterpret_cast<uint4*>(ob + seg * 256 + lane * 8) = pk;
    }
}

// ---------------------------------------------------------------------------
// 2) HMMA GEMM 128x128x64/iter, 3-stage cp.async, single sync per iter,
//    fused ex2 epilogue (split diag/non-diag paths). 8 warps, 2x4 grid.
// ---------------------------------------------------------------------------
__global__ __launch_bounds__(256, 2) void gemm_kernel() {
    extern __shared__ char smem[];
    const uint32_t sb = smem_u32(smem);
    const int tid = threadIdx.x;
    const int warp = tid >> 5, lane = tid & 31;
    const int wy = warp >> 2, wx = warp & 3;        // 2 x 4 warp grid
    const int bi = blockIdx.y, bj = blockIdx.x;

    const char* Ag = (const char*)(g_zh + (size_t)bi * BM * DIM);
    const char* Bg = (const char*)(g_zh + (size_t)(NROWS + bj * BN) * DIM);

    // cp.async mapping: 128B rows = 8 x 16B chunks; phys = ch ^ (row & 7).
    const int row0 = tid >> 3, ch0 = tid & 7;       // rows 0..31
    uint32_t s_off[4];
    size_t   g_off[4];
    #pragma unroll
    for (int r = 0; r < 4; r++) {
        int row = row0 + r * 32;
        int ph  = ch0 ^ (row & 7);
        s_off[r] = row * 128 + ph * 16;
        g_off[r] = (size_t)row * DIM * 2 + ch0 * 16;
    }

    float acc[4][4][4];
    #pragma unroll
    for (int mt = 0; mt < 4; mt++)
        #pragma unroll
        for (int nt = 0; nt < 4; nt++)
            #pragma unroll
            for (int q = 0; q < 4; q++) acc[mt][nt][q] = 0.f;

    // prologue: stages 0,1
    #pragma unroll
    for (int s = 0; s < NSTAGE - 1; s++) {
        uint32_t As = sb + s * STAGE_BYTES;
        uint32_t Bs = As + STAGE_A_BYTES;
        size_t kb = (size_t)(s * BK) * 2;
        #pragma unroll
        for (int r = 0; r < 4; r++) {
            CPA16(As + s_off[r], Ag + g_off[r] + kb);
            CPA16(Bs + s_off[r], Bg + g_off[r] + kb);
        }
        CPA_COMMIT();
    }

    // ldmatrix lane components
    const int rl  = lane & 15;                  // A row within 16
    const int ahi = lane >> 4;                  // A 16B k-chunk select
    const int nl  = (lane & 7) | ((lane >> 4) << 3);   // B n within 16
    const int bhi = (lane >> 3) & 1;

    for (int kc = 0; kc < NITER; kc++) {
        const int st = kc % NSTAGE;
        if (kc < NITER - 1) { CPA_WAIT1(); } else { CPA_WAIT0(); }
        __syncthreads();
        if (kc + NSTAGE - 1 < NITER) {
            const int sn = (kc + NSTAGE - 1) % NSTAGE;
            uint32_t As = sb + sn * STAGE_BYTES;
            uint32_t Bs = As + STAGE_A_BYTES;
            size_t kb = (size_t)((kc + NSTAGE - 1) * BK) * 2;
            #pragma unroll
            for (int r = 0; r < 4; r++) {
                CPA16(As + s_off[r], Ag + g_off[r] + kb);
                CPA16(Bs + s_off[r], Bg + g_off[r] + kb);
            }
            CPA_COMMIT();
        }
        const uint32_t As = sb + st * STAGE_BYTES;
        const uint32_t Bs = As + STAGE_A_BYTES;
        #pragma unroll
        for (int ks = 0; ks < 4; ks++) {
            uint32_t a[4][4], b[2][4];
            uint32_t a_addr = As + (wy * 64 + rl) * 128 + (((ks * 2 + ahi) ^ (rl & 7)) * 16);
            #pragma unroll
            for (int mt = 0; mt < 4; mt++) ldsm4(a[mt], a_addr + mt * 2048);
            uint32_t b_addr = Bs + (wx * 32 + nl) * 128 + (((ks * 2 + bhi) ^ (nl & 7)) * 16);
            #pragma unroll
            for (int p = 0; p < 2; p++) ldsm4(b[p], b_addr + p * 2048);
            #pragma unroll
            for (int mt = 0; mt < 4; mt++)
                #pragma unroll
                for (int nt = 0; nt < 4; nt++)
                    mma16816(acc[mt][nt], a[mt], &b[nt >> 1][(nt & 1) * 2]);
        }
    }

    // ---------------- epilogue: ex2 row-sums (+ diagonal on diag tiles) ----
    __syncthreads();
    float* sred = (float*)smem;                // 128 rows x 4 wx
    if (bi != bj) {
        // hot path (4032/4096 tiles): no compares, no conditional stores
        #pragma unroll
        for (int mt = 0; mt < 4; mt++) {
            int ra = wy * 64 + mt * 16 + (lane >> 2);
            float sA = 0.f, sB = 0.f;
            #pragma unroll
            for (int nt = 0; nt < 4; nt++) {
                sA += ex2(acc[mt][nt][0]) + ex2(acc[mt][nt][1]);
                sB += ex2(acc[mt][nt][2]) + ex2(acc[mt][nt][3]);
            }
            sA += __shfl_xor_sync(0xffffffffu, sA, 1);
            sA += __shfl_xor_sync(0xffffffffu, sA, 2);
            sB += __shfl_xor_sync(0xffffffffu, sB, 1);
            sB += __shfl_xor_sync(0xffffffffu, sB, 2);
            if ((lane & 3) == 0) {
                sred[ra * 4 + wx] = sA;
                sred[(ra + 8) * 4 + wx] = sB;
            }
        }
    } else {
        // diag path (64 tiles): identical arithmetic + diagonal extraction
        #pragma unroll
        for (int mt = 0; mt < 4; mt++) {
            int ra = wy * 64 + mt * 16 + (lane >> 2);
            float sA = 0.f, sB = 0.f;
            #pragma unroll
            for (int nt = 0; nt < 4; nt++) {
                int c0 = wx * 32 + nt * 8 + 2 * (lane & 3);
                float v0 = acc[mt][nt][0], v1 = acc[mt][nt][1];
                float v2 = acc[mt][nt][2], v3 = acc[mt][nt][3];
                sA += ex2(v0) + ex2(v1);
                sB += ex2(v2) + ex2(v3);
                if (ra == c0)         g_diag[bi * BM + ra] = v0;
                if (ra == c0 + 1)     g_diag[bi * BM + ra] = v1;
                if (ra + 8 == c0)     g_diag[bi * BM + ra + 8] = v2;
                if (ra + 8 == c0 + 1) g_diag[bi * BM + ra + 8] = v3;
            }
            sA += __shfl_xor_sync(0xffffffffu, sA, 1);
            sA += __shfl_xor_sync(0xffffffffu, sA, 2);
            sB += __shfl_xor_sync(0xffffffffu, sB, 1);
            sB += __shfl_xor_sync(0xffffffffu, sB, 2);
            if ((lane & 3) == 0) {
                sred[ra * 4 + wx] = sA;
                sred[(ra + 8) * 4 + wx] = sB;
            }
        }
    }
    __syncthreads();
    if (tid < BM) {
        float s = sred[tid * 4 + 0] + sred[tid * 4 + 1]
                + sred[tid * 4 + 2] + sred[tid * 4 + 3];
        g_pe[(size_t)bj * NROWS + bi * BM + tid] = s;
    }
}

// ---------------------------------------------------------------------------
// 3) Finalize (ALPHA=1 -> alpha=p_ij, BETA=0 -> neg_sim drops).
//    pe = ex2(scaled diag) is bitwise-identical to the epilogue's term, so
//    the row-sum subtraction cancels exactly. pos recovered via * ln2.
// ---------------------------------------------------------------------------
__global__ __launch_bounds__(1024) void finalize_kernel(float* __restrict__ out) {
    __shared__ float spart[8][128];
    __shared__ float sl[128], sp[128];
    __shared__ bool is_last;
    int rl = threadIdx.x & 127, tg = threadIdx.x >> 7;
    int r = blockIdx.x * 128 + rl;
    float se = 0.f;
    #pragma unroll
    for (int t = tg * 8; t < tg * 8 + 8; t++) se += g_pe[(size_t)t * NROWS + r];
    spart[tg][rl] = se;
    __syncthreads();
    if (threadIdx.x < 128) {
        float tot = 0.f;
        #pragma unroll
        for (int t = 0; t < 8; t++) tot += spart[t][rl];
        float dv  = g_diag[r];                 // log2e-scaled cosine
        float pe  = ex2(dv);                   // bitwise-identical to epilogue term
        float pos = dv * LN2;                  // true cosine similarity
        float p   = pe / (tot - pe);
        sl[rl] = -logf(p) - p * pos;
        sp[rl] = p;
    }
    __syncthreads();
    #pragma unroll
    for (int o = 64; o; o >>= 1) {
        if (threadIdx.x < o) {
            sl[threadIdx.x] += sl[threadIdx.x + o];
            sp[threadIdx.x] += sp[threadIdx.x + o];
        }
        __syncthreads();
    }
    if (threadIdx.x == 0) {
        g_bl[blockIdx.x] = sl[0];
        g_bp[blockIdx.x] = sp[0];
        __threadfence();
        unsigned int prev = atomicAdd(&g_cnt, 1u);
        is_last = (prev == NFBLK - 1);
    }
    __syncthreads();
    if (is_last && threadIdx.x == 0) {
        float tl = 0.f, tp = 0.f;
        #pragma unroll
        for (int b = 0; b < NFBLK; b++) { tl += g_bl[b]; tp += g_bp[b]; }
        out[0] = tl / (float)NROWS;
        out[1] = tp / (float)NROWS;
    }
}

// ---------------------------------------------------------------------------
extern "C" void kernel_launch(void* const* d_in, const int* in_sizes, int n_in,
                              void* d_out, int out_size) {
    const float* z = (const float*)d_in[0];
    float* out = (float*)d_out;

    cudaFuncSetAttribute(gemm_kernel, cudaFuncAttributeMaxDynamicSharedMemorySize, SMEM_TOTAL);

    normconv_kernel<<<2 * NROWS / 8, 256>>>(z);
    gemm_kernel<<<dim3(NROWS / BN, NROWS / BM), 256, SMEM_TOTAL>>>();
    finalize_kernel<<<NFBLK, 1024>>>(out);
}